// round 9
// baseline (speedup 1.0000x reference)
#include <cuda_runtime.h>
#include <cstdint>

// mean_aggregator: out[b,:] = (1/32) * sum_s emb[neighbors[b,s], :]
// B=50000, S=32, D=128, emb 500000x128 fp32 (256 MB > 126 MB L2).
//
// Persistent one-wave kernel, position-windowed sorted gather.
// R9 = R7's r-outer/p-inner loop order (deep LDG batching under the 64-reg
// cap: one acc chain + 8-11 loads live at a time) + R8's NW=3 windows
// (2 fences, measured-lower DRAM bytes 309 MB).

#define THREADS 256
#define WPB (THREADS / 32)
#define ROWS 11
#define NW 3
#define SPIN_LIMIT (1u << 18)

__device__ unsigned g_bar[NW];     // NW-1 fence counters + 1 exit counter

__device__ __forceinline__ void grid_fence(int b, int nblocks)
{
    __syncthreads();
    if (threadIdx.x == 0) {
        const unsigned old = atomicAdd(&g_bar[b], 1u);
        if (old == (unsigned)(nblocks - 1) && b > 0)
            g_bar[b - 1] = 0;                  // all blocks passed fence b-1
        unsigned tries = 0;
        while (*(volatile unsigned*)&g_bar[b] < (unsigned)nblocks &&
               tries < SPIN_LIMIT) {
            ++tries;
            __nanosleep(32);
        }
    }
    __syncthreads();
}

template<int BASE, int CNT>
__device__ __forceinline__ void gather_window(const int (*s_row)[32],
                                              const float4* __restrict__ emb,
                                              float4* acc, int lane)
{
    #pragma unroll
    for (int r = 0; r < ROWS; ++r) {           // r-outer: 1 acc chain live,
        #pragma unroll                         // CNT loads batched in flight
        for (int p = 0; p < CNT; ++p) {
            const int n = s_row[r][BASE + p];  // LDS broadcast
            const float4 v = __ldg(&emb[(size_t)n * 32 + lane]);
            acc[r].x += v.x;
            acc[r].y += v.y;
            acc[r].z += v.z;
            acc[r].w += v.w;
        }
    }
}

__global__ __launch_bounds__(THREADS, 4)
void mean_agg_poswin(const int* __restrict__ neighbors,
                     const float4* __restrict__ emb,   // [N, 32] float4
                     float4* __restrict__ out,         // [B, 32] float4
                     int batch)
{
    __shared__ int s_ids[WPB][ROWS][32];

    const int wid  = threadIdx.x >> 5;
    const int lane = threadIdx.x & 31;
    const int nblocks = gridDim.x;
    const int W   = nblocks * WPB;
    const int gw  = blockIdx.x * WPB + wid;

    // ---- load + warp-bitonic sort each owned row's 32 ids ----
    #pragma unroll
    for (int r = 0; r < ROWS; ++r) {
        const int row = gw + r * W;
        int v = (row < batch) ? neighbors[row * 32 + lane] : 0;

        #pragma unroll
        for (int k = 2; k <= 32; k <<= 1) {
            #pragma unroll
            for (int j = k >> 1; j > 0; j >>= 1) {
                const int other  = __shfl_xor_sync(0xffffffffu, v, j);
                const bool up    = ((lane & k) == 0);
                const bool lower = ((lane & j) == 0);
                v = ((lower == up) ? min(v, other) : max(v, other));
            }
        }
        s_ids[wid][r][lane] = v;
    }
    __syncthreads();

    float4 acc[ROWS];
    #pragma unroll
    for (int r = 0; r < ROWS; ++r)
        acc[r] = make_float4(0.f, 0.f, 0.f, 0.f);

    // ---- 3 position-windows (11/11/10), fences between ----
    gather_window<0, 11>(s_ids[wid], emb, acc, lane);
    grid_fence(0, nblocks);
    gather_window<11, 11>(s_ids[wid], emb, acc, lane);
    grid_fence(1, nblocks);
    gather_window<22, 10>(s_ids[wid], emb, acc, lane);

    // ---- write means ----
    const float inv = 1.0f / 32.0f;
    #pragma unroll
    for (int r = 0; r < ROWS; ++r) {
        const int row = gw + r * W;
        if (row < batch) {
            float4 a = acc[r];
            a.x *= inv; a.y *= inv; a.z *= inv; a.w *= inv;
            out[(size_t)row * 32 + lane] = a;
        }
    }

    // ---- exit: reset fence state for next graph replay ----
    __syncthreads();
    if (threadIdx.x == 0) {
        const unsigned old = atomicAdd(&g_bar[NW - 1], 1u);
        if (old == (unsigned)(nblocks - 1)) {
            g_bar[NW - 2] = 0;
            g_bar[NW - 1] = 0;
        }
    }
}

// Fallback (R1 kernel) for shapes exceeding persistent capacity.
__global__ __launch_bounds__(THREADS)
void mean_agg_naive(const int* __restrict__ neighbors,
                    const float4* __restrict__ emb,
                    float4* __restrict__ out, int batch)
{
    const int warp = (blockIdx.x * blockDim.x + threadIdx.x) >> 5;
    const int lane = threadIdx.x & 31;
    if (warp >= batch) return;
    const int my = neighbors[warp * 32 + lane];
    float4 acc = make_float4(0.f, 0.f, 0.f, 0.f);
    #pragma unroll
    for (int s = 0; s < 32; ++s) {
        const int n = __shfl_sync(0xffffffffu, my, s);
        const float4 v = __ldg(&emb[(size_t)n * 32 + lane]);
        acc.x += v.x; acc.y += v.y; acc.z += v.z; acc.w += v.w;
    }
    const float inv = 1.0f / 32.0f;
    acc.x *= inv; acc.y *= inv; acc.z *= inv; acc.w *= inv;
    out[(size_t)warp * 32 + lane] = acc;
}

extern "C" void kernel_launch(void* const* d_in, const int* in_sizes, int n_in,
                              void* d_out, int out_size)
{
    const int* neighbors = (const int*)d_in[0];     // [B, 32] int32
    const float4* emb    = (const float4*)d_in[1];  // [N, 128] fp32 as float4

    const int batch = in_sizes[0] / 32;             // 50000

    int sms = 0;
    if (cudaDeviceGetAttribute(&sms, cudaDevAttrMultiProcessorCount, 0) !=
            cudaSuccess || sms <= 0)
        sms = 148;

    const int nblocks = sms * 4;                    // one guaranteed wave
    const long long capacity = (long long)nblocks * WPB * ROWS;

    if ((long long)batch <= capacity) {
        mean_agg_poswin<<<nblocks, THREADS>>>(neighbors, emb,
                                              (float4*)d_out, batch);
    } else {
        const int blocks = (batch + WPB - 1) / WPB;
        mean_agg_naive<<<blocks, THREADS>>>(neighbors, emb,
                                            (float4*)d_out, batch);
    }
}

// round 11
// speedup vs baseline: 1.0546x; 1.0546x over previous
#include <cuda_runtime.h>
#include <cstdint>

// mean_aggregator: out[b,:] = (1/32) * sum_s emb[neighbors[b,s], :]
// B=50000, S=32, D=128, emb 500000x128 fp32 (256 MB > 126 MB L2).
//
// Persistent one-wave kernel, position-windowed sorted gather (R7 WIN config:
// 4 windows x 8 positions, r-outer/p-inner -> 8-load batches fit the 64-reg
// budget). R10 delta: drop the last grid fence (windows 2,3 contiguous) —
// one fewer full-grid convergence tail, small DRAM-byte cost absorbed by
// headroom. L2 service (~850 MB of gathers) is the wall (~94% of LTS cap).

#define THREADS 256
#define WPB (THREADS / 32)
#define ROWS 11
#define NFENCE 2                   // fences after window 0 and window 1
#define SPIN_LIMIT (1u << 17)

__device__ unsigned g_bar[NFENCE + 1];   // fence counters + exit counter

__device__ __forceinline__ void grid_fence(int b, int nblocks)
{
    __syncthreads();
    if (threadIdx.x == 0) {
        const unsigned old = atomicAdd(&g_bar[b], 1u);
        if (old == (unsigned)(nblocks - 1) && b > 0)
            g_bar[b - 1] = 0;                  // all blocks passed fence b-1
        unsigned tries = 0;
        while (*(volatile unsigned*)&g_bar[b] < (unsigned)nblocks &&
               tries < SPIN_LIMIT) {
            ++tries;
            __nanosleep(64);
        }
    }
    __syncthreads();
}

template<int BASE, int CNT>
__device__ __forceinline__ void gather_window(const int (*s_row)[32],
                                              const float4* __restrict__ emb,
                                              float4* acc, int lane)
{
    #pragma unroll
    for (int r = 0; r < ROWS; ++r) {           // r-outer: 1 acc chain live,
        #pragma unroll                         // 8-load batch in flight
        for (int p = 0; p < CNT; ++p) {
            const int n = s_row[r][BASE + p];  // LDS broadcast
            const float4 v = __ldg(&emb[(size_t)n * 32 + lane]);
            acc[r].x += v.x;
            acc[r].y += v.y;
            acc[r].z += v.z;
            acc[r].w += v.w;
        }
    }
}

__global__ __launch_bounds__(THREADS, 4)
void mean_agg_poswin(const int* __restrict__ neighbors,
                     const float4* __restrict__ emb,   // [N, 32] float4
                     float4* __restrict__ out,         // [B, 32] float4
                     int batch)
{
    __shared__ int s_ids[WPB][ROWS][32];

    const int wid  = threadIdx.x >> 5;
    const int lane = threadIdx.x & 31;
    const int nblocks = gridDim.x;
    const int W   = nblocks * WPB;
    const int gw  = blockIdx.x * WPB + wid;

    // ---- load + warp-bitonic sort each owned row's 32 ids ----
    #pragma unroll
    for (int r = 0; r < ROWS; ++r) {
        const int row = gw + r * W;
        int v = (row < batch) ? neighbors[row * 32 + lane] : 0;

        #pragma unroll
        for (int k = 2; k <= 32; k <<= 1) {
            #pragma unroll
            for (int j = k >> 1; j > 0; j >>= 1) {
                const int other  = __shfl_xor_sync(0xffffffffu, v, j);
                const bool up    = ((lane & k) == 0);
                const bool lower = ((lane & j) == 0);
                v = ((lower == up) ? min(v, other) : max(v, other));
            }
        }
        s_ids[wid][r][lane] = v;
    }
    __syncthreads();

    float4 acc[ROWS];
    #pragma unroll
    for (int r = 0; r < ROWS; ++r)
        acc[r] = make_float4(0.f, 0.f, 0.f, 0.f);

    // ---- 4 position-windows of 8; fences after w0, w1 only ----
    gather_window<0,  8>(s_ids[wid], emb, acc, lane);
    grid_fence(0, nblocks);
    gather_window<8,  8>(s_ids[wid], emb, acc, lane);
    grid_fence(1, nblocks);
    gather_window<16, 8>(s_ids[wid], emb, acc, lane);
    gather_window<24, 8>(s_ids[wid], emb, acc, lane);

    // ---- write means ----
    const float inv = 1.0f / 32.0f;
    #pragma unroll
    for (int r = 0; r < ROWS; ++r) {
        const int row = gw + r * W;
        if (row < batch) {
            float4 a = acc[r];
            a.x *= inv; a.y *= inv; a.z *= inv; a.w *= inv;
            out[(size_t)row * 32 + lane] = a;
        }
    }

    // ---- exit: reset fence state for next graph replay ----
    __syncthreads();
    if (threadIdx.x == 0) {
        const unsigned old = atomicAdd(&g_bar[NFENCE], 1u);
        if (old == (unsigned)(nblocks - 1)) {
            g_bar[NFENCE - 1] = 0;
            g_bar[NFENCE] = 0;
        }
    }
}

// Fallback (R1 kernel) for shapes exceeding persistent capacity.
__global__ __launch_bounds__(THREADS)
void mean_agg_naive(const int* __restrict__ neighbors,
                    const float4* __restrict__ emb,
                    float4* __restrict__ out, int batch)
{
    const int warp = (blockIdx.x * blockDim.x + threadIdx.x) >> 5;
    const int lane = threadIdx.x & 31;
    if (warp >= batch) return;
    const int my = neighbors[warp * 32 + lane];
    float4 acc = make_float4(0.f, 0.f, 0.f, 0.f);
    #pragma unroll
    for (int s = 0; s < 32; ++s) {
        const int n = __shfl_sync(0xffffffffu, my, s);
        const float4 v = __ldg(&emb[(size_t)n * 32 + lane]);
        acc.x += v.x; acc.y += v.y; acc.z += v.z; acc.w += v.w;
    }
    const float inv = 1.0f / 32.0f;
    acc.x *= inv; acc.y *= inv; acc.z *= inv; acc.w *= inv;
    out[(size_t)warp * 32 + lane] = acc;
}

extern "C" void kernel_launch(void* const* d_in, const int* in_sizes, int n_in,
                              void* d_out, int out_size)
{
    const int* neighbors = (const int*)d_in[0];     // [B, 32] int32
    const float4* emb    = (const float4*)d_in[1];  // [N, 128] fp32 as float4

    const int batch = in_sizes[0] / 32;             // 50000

    int sms = 0;
    if (cudaDeviceGetAttribute(&sms, cudaDevAttrMultiProcessorCount, 0) !=
            cudaSuccess || sms <= 0)
        sms = 148;

    const int nblocks = sms * 4;                    // one guaranteed wave
    const long long capacity = (long long)nblocks * WPB * ROWS;

    if ((long long)batch <= capacity) {
        mean_agg_poswin<<<nblocks, THREADS>>>(neighbors, emb,
                                              (float4*)d_out, batch);
    } else {
        const int blocks = (batch + WPB - 1) / WPB;
        mean_agg_naive<<<blocks, THREADS>>>(neighbors, emb,
                                            (float4*)d_out, batch);
    }
}

// round 12
// speedup vs baseline: 1.5002x; 1.4225x over previous
#include <cuda_runtime.h>
#include <cstdint>

// mean_aggregator: out[b,:] = (1/32) * sum_s emb[neighbors[b,s], :]
// B=50000, S=32, D=128, emb 500000x128 fp32 (256 MB > 126 MB L2).
//
// Persistent one-wave kernel, position-windowed sorted gather:
//  - each warp owns ROWS rows; ids warp-bitonic sorted into smem once
//  - float4 accumulators live in registers for the whole kernel
//  - window w gathers sorted POSITIONS [8w, 8w+8): static trip count ->
//    fully unrolled independent loads (8-load batches fit the 64-reg budget)
//  - sorted order makes position ~ value (order statistics); soft grid fences
//    between windows keep all resident warps in the same ~64-100 MB value
//    region -> L2-resident window, each table row ~one DRAM fetch.
//  - fences are pure locality hints: correctness never depends on them.
//
// NOTE: gather loops are INLINE in the kernel body with a runtime window
// loop — refactoring them into a templated helper (R8-R10) changed ptxas
// load batching and cost ~35 us at identical DRAM bytes. Do not refactor.

#define THREADS 256
#define WPB (THREADS / 32)
#define ROWS 11
#define NW 4                       // 4 windows x 8 positions
#define POS_PER_W (32 / NW)
#define SPIN_LIMIT (1u << 17)

__device__ unsigned g_bar[NW];     // NW-1 fence counters + 1 exit counter

__device__ __forceinline__ void grid_fence(int b, int nblocks)
{
    __syncthreads();
    if (threadIdx.x == 0) {
        const unsigned old = atomicAdd(&g_bar[b], 1u);
        if (old == (unsigned)(nblocks - 1) && b > 0)
            g_bar[b - 1] = 0;                  // all blocks passed fence b-1
        unsigned tries = 0;
        while (*(volatile unsigned*)&g_bar[b] < (unsigned)nblocks &&
               tries < SPIN_LIMIT) {
            ++tries;
            __nanosleep(64);
        }
    }
    __syncthreads();
}

__global__ __launch_bounds__(THREADS, 4)
void mean_agg_poswin(const int* __restrict__ neighbors,
                     const float4* __restrict__ emb,   // [N, 32] float4
                     float4* __restrict__ out,         // [B, 32] float4
                     int batch)
{
    __shared__ int s_ids[WPB][ROWS][32];

    const int wid  = threadIdx.x >> 5;
    const int lane = threadIdx.x & 31;
    const int nblocks = gridDim.x;
    const int W   = nblocks * WPB;
    const int gw  = blockIdx.x * WPB + wid;

    // ---- load + warp-bitonic sort each owned row's 32 ids ----
    #pragma unroll
    for (int r = 0; r < ROWS; ++r) {
        const int row = gw + r * W;
        // Sentinel id 0 for inactive rows: harmless extra loads, result unused.
        int v = (row < batch) ? neighbors[row * 32 + lane] : 0;

        #pragma unroll
        for (int k = 2; k <= 32; k <<= 1) {
            #pragma unroll
            for (int j = k >> 1; j > 0; j >>= 1) {
                const int other  = __shfl_xor_sync(0xffffffffu, v, j);
                const bool up    = ((lane & k) == 0);
                const bool lower = ((lane & j) == 0);
                v = ((lower == up) ? min(v, other) : max(v, other));
            }
        }
        s_ids[wid][r][lane] = v;
    }
    __syncthreads();

    float4 acc[ROWS];
    #pragma unroll
    for (int r = 0; r < ROWS; ++r)
        acc[r] = make_float4(0.f, 0.f, 0.f, 0.f);

    // ---- position-windowed gather: static, fully unrolled ----
    for (int w = 0; w < NW; ++w) {
        const int base = w * POS_PER_W;
        #pragma unroll
        for (int r = 0; r < ROWS; ++r) {
            #pragma unroll
            for (int p = 0; p < POS_PER_W; ++p) {
                const int n = s_ids[wid][r][base + p];     // LDS broadcast
                const float4 v = __ldg(&emb[(size_t)n * 32 + lane]);
                acc[r].x += v.x;
                acc[r].y += v.y;
                acc[r].z += v.z;
                acc[r].w += v.w;
            }
        }
        if (w < NW - 1) grid_fence(w, nblocks);
    }

    // ---- write means ----
    const float inv = 1.0f / 32.0f;
    #pragma unroll
    for (int r = 0; r < ROWS; ++r) {
        const int row = gw + r * W;
        if (row < batch) {
            float4 a = acc[r];
            a.x *= inv; a.y *= inv; a.z *= inv; a.w *= inv;
            out[(size_t)row * 32 + lane] = a;
        }
    }

    // ---- exit: reset fence state for next graph replay ----
    __syncthreads();
    if (threadIdx.x == 0) {
        const unsigned old = atomicAdd(&g_bar[NW - 1], 1u);
        if (old == (unsigned)(nblocks - 1)) {
            g_bar[NW - 2] = 0;
            g_bar[NW - 1] = 0;
        }
    }
}

// Fallback (R1 kernel) for shapes exceeding persistent capacity.
__global__ __launch_bounds__(THREADS)
void mean_agg_naive(const int* __restrict__ neighbors,
                    const float4* __restrict__ emb,
                    float4* __restrict__ out, int batch)
{
    const int warp = (blockIdx.x * blockDim.x + threadIdx.x) >> 5;
    const int lane = threadIdx.x & 31;
    if (warp >= batch) return;
    const int my = neighbors[warp * 32 + lane];
    float4 acc = make_float4(0.f, 0.f, 0.f, 0.f);
    #pragma unroll
    for (int s = 0; s < 32; ++s) {
        const int n = __shfl_sync(0xffffffffu, my, s);
        const float4 v = __ldg(&emb[(size_t)n * 32 + lane]);
        acc.x += v.x; acc.y += v.y; acc.z += v.z; acc.w += v.w;
    }
    const float inv = 1.0f / 32.0f;
    acc.x *= inv; acc.y *= inv; acc.z *= inv; acc.w *= inv;
    out[(size_t)warp * 32 + lane] = acc;
}

extern "C" void kernel_launch(void* const* d_in, const int* in_sizes, int n_in,
                              void* d_out, int out_size)
{
    const int* neighbors = (const int*)d_in[0];     // [B, 32] int32
    const float4* emb    = (const float4*)d_in[1];  // [N, 128] fp32 as float4

    const int batch = in_sizes[0] / 32;             // 50000

    int sms = 0;
    if (cudaDeviceGetAttribute(&sms, cudaDevAttrMultiProcessorCount, 0) !=
            cudaSuccess || sms <= 0)
        sms = 148;

    const int nblocks = sms * 4;                    // one guaranteed wave
    const long long capacity = (long long)nblocks * WPB * ROWS;

    if ((long long)batch <= capacity) {
        mean_agg_poswin<<<nblocks, THREADS>>>(neighbors, emb,
                                              (float4*)d_out, batch);
    } else {
        const int blocks = (batch + WPB - 1) / WPB;
        mean_agg_naive<<<blocks, THREADS>>>(neighbors, emb,
                                            (float4*)d_out, batch);
    }
}